// round 10
// baseline (speedup 1.0000x reference)
#include <cuda_runtime.h>
#include <cstdint>

// FixedRadiusNearNeighbors: B=8, N=16384, S=2048, radius 0.1, K=64.
// First 64 ascending indices with sqrdist <= 0.01f, padded with first hit,
// float32 output. Distance arithmetic FROZEN (bit-identical to R6 pass):
//   cc  = ((cx*cx + cy*cy) + cz*cz)            f32 RN mul/add
//   dot = fma(pz,cz, fma(py,cy, mul(px,cx)))   [fma(a,b,0) == mul_rn]
//   d   = fma(dot,-2,cc) + pp   [== (cc-2*dot)+pp, 2*dot exact]
//   pp  = ((px*px + py*py) + pz*pz)            f32 RN mul/add
//   hit = d <= 0.01f
//
// R10: 4 points/lane/iter (2 pair LDS.128), per-query any-gate, shfl-free
// first-hit, finished queries killed via cc=1e30 (branch-free hot path).

#define BATCH  8
#define NPTS   16384
#define NQ     2048
#define NNB    64
#define TILE   2048
#define NPAIR  (TILE / 2)
#define WPB    8
#define QPW    2
#define QPB    (WPB * QPW)       // 16
#define R2     0.01f

__device__ __forceinline__ uint64_t pk2(float a, float b) {
    return (uint64_t)__float_as_uint(a) | ((uint64_t)__float_as_uint(b) << 32);
}
__device__ __forceinline__ float lo2(uint64_t v) { return __uint_as_float((uint32_t)v); }
__device__ __forceinline__ float hi2(uint64_t v) { return __uint_as_float((uint32_t)(v >> 32)); }
__device__ __forceinline__ uint64_t mul2(uint64_t a, uint64_t b) {
    uint64_t d;
    asm("mul.rn.f32x2 %0, %1, %2;" : "=l"(d) : "l"(a), "l"(b));
    return d;
}
__device__ __forceinline__ uint64_t fma2(uint64_t a, uint64_t b, uint64_t c) {
    uint64_t d;
    asm("fma.rn.f32x2 %0, %1, %2, %3;" : "=l"(d) : "l"(a), "l"(b), "l"(c));
    return d;
}
__device__ __forceinline__ uint64_t add2(uint64_t a, uint64_t b) {
    uint64_t d;
    asm("add.rn.f32x2 %0, %1, %2;" : "=l"(d) : "l"(a), "l"(b));
    return d;
}
__device__ __forceinline__ void lds128(uint64_t& a, uint64_t& b, const float4* p) {
    uint32_t sa = (uint32_t)__cvta_generic_to_shared(p);
    asm volatile("ld.shared.v2.b64 {%0, %1}, [%2];" : "=l"(a), "=l"(b) : "r"(sa));
}

// Packed distance for one query against one pair {lo,hi}.
__device__ __forceinline__ uint64_t dist2(uint64_t x2, uint64_t y2, uint64_t z2,
                                          uint64_t pp2, uint64_t cx2, uint64_t cy2,
                                          uint64_t cz2, uint64_t cc2, uint64_t neg2) {
    uint64_t t = mul2(x2, cx2);
    t = fma2(y2, cy2, t);
    t = fma2(z2, cz2, t);
    t = fma2(t, neg2, cc2);
    return add2(t, pp2);
}

__global__ __launch_bounds__(256)
void frnn_kernel(const float* __restrict__ pos,
                 const int*   __restrict__ cent,
                 float*       __restrict__ out)
{
    __shared__ float4 arrA[NPAIR];   // {x0, x1, y0, y1} for pair (p, p+32)
    __shared__ float4 arrB[NPAIR];   // {z0, z1, pp0, pp1}
    __shared__ int done_count;

    const int lane = threadIdx.x & 31;
    const int warp = threadIdx.x >> 5;
    const int q0   = blockIdx.x * QPB + warp * QPW;
    const int b    = q0 >> 11;
    const float* posb = pos + (size_t)b * NPTS * 3;

    const int ci0 = cent[q0], ci1 = cent[q0 + 1];
    const float a0x = posb[ci0*3+0], a0y = posb[ci0*3+1], a0z = posb[ci0*3+2];
    const float a1x = posb[ci1*3+0], a1y = posb[ci1*3+1], a1z = posb[ci1*3+2];
    const float cc0 = __fadd_rn(__fadd_rn(__fmul_rn(a0x,a0x), __fmul_rn(a0y,a0y)),
                                __fmul_rn(a0z,a0z));
    const float cc1 = __fadd_rn(__fadd_rn(__fmul_rn(a1x,a1x), __fmul_rn(a1y,a1y)),
                                __fmul_rn(a1z,a1z));
    const uint64_t c0x2 = pk2(a0x,a0x), c0y2 = pk2(a0y,a0y), c0z2 = pk2(a0z,a0z);
    const uint64_t c1x2 = pk2(a1x,a1x), c1y2 = pk2(a1y,a1y), c1z2 = pk2(a1z,a1z);
    const uint64_t neg2 = pk2(-2.0f,-2.0f);
    const uint64_t KILL = pk2(1e30f, 1e30f);

    uint64_t cc02 = pk2(cc0,cc0), cc12 = pk2(cc1,cc1);

    float* orow0 = out + (size_t)q0 * NNB;
    float* orow1 = orow0 + NNB;

    if (threadIdx.x == 0) done_count = 0;

    int   cnt0 = 0,     cnt1 = 0;
    float first0 = 0.f, first1 = 0.f;

    for (int base = 0; base < NPTS; base += TILE) {
        __syncthreads();
        if (done_count == QPB) break;

        // Tile load: pair (p, p+32); pp with frozen rounding.
        const float* src = posb + (size_t)base * 3;
        #pragma unroll
        for (int s = threadIdx.x; s < NPAIR; s += 256) {
            int j = s >> 5, l = s & 31;
            int p0 = (j << 6) + l;
            const float* g0 = src + p0 * 3;
            const float* g1 = g0 + 96;
            float x0 = g0[0], y0 = g0[1], z0 = g0[2];
            float x1 = g1[0], y1 = g1[1], z1 = g1[2];
            float pp0 = __fadd_rn(__fadd_rn(__fmul_rn(x0,x0), __fmul_rn(y0,y0)),
                                  __fmul_rn(z0,z0));
            float pp1 = __fadd_rn(__fadd_rn(__fmul_rn(x1,x1), __fmul_rn(y1,y1)),
                                  __fmul_rn(z1,z1));
            arrA[s] = make_float4(x0, x1, y0, y1);
            arrB[s] = make_float4(z0, z1, pp0, pp1);
        }
        __syncthreads();

        if (cnt0 >= NNB && cnt1 >= NNB) continue;   // idle warp still loads tiles

        #pragma unroll 4
        for (int it = 0; it < TILE / 128; ++it) {   // 128 points/iter/warp
            const int s0 = (it << 6) + lane;        // pair block j=2it  -> +0/+32
            const int s1 = s0 + 32;                 // pair block j=2it+1-> +64/+96
            uint64_t xA, yA, zA, ppA, xB, yB, zB, ppB;
            lds128(xA, yA, arrA + s0);
            lds128(zA, ppA, arrB + s0);
            lds128(xB, yB, arrA + s1);
            lds128(zB, ppB, arrB + s1);

            const int i0base = base + (it << 7);

            // ---- query 0 ----
            {
                uint64_t dA = dist2(xA, yA, zA, ppA, c0x2, c0y2, c0z2, cc02, neg2);
                uint64_t dB = dist2(xB, yB, zB, ppB, c0x2, c0y2, c0z2, cc02, neg2);
                float v0 = lo2(dA), v1 = hi2(dA), v2 = lo2(dB), v3 = hi2(dB);
                bool any = (v0 <= R2) | (v1 <= R2) | (v2 <= R2) | (v3 <= R2);
                if (__any_sync(0xffffffffu, any)) {
                    unsigned mA = __ballot_sync(0xffffffffu, v0 <= R2);
                    unsigned mB = __ballot_sync(0xffffffffu, v1 <= R2);
                    unsigned mC = __ballot_sync(0xffffffffu, v2 <= R2);
                    unsigned mD = __ballot_sync(0xffffffffu, v3 <= R2);
                    const unsigned below = (1u << lane) - 1u;
                    if (cnt0 == 0) {
                        int fi = mA ? i0base + (__ffs(mA) - 1)
                               : mB ? i0base + 32 + (__ffs(mB) - 1)
                               : mC ? i0base + 64 + (__ffs(mC) - 1)
                                    : i0base + 96 + (__ffs(mD) - 1);
                        first0 = (float)fi;
                    }
                    int c = cnt0;
                    if (mA & (1u << lane)) {
                        int slot = c + __popc(mA & below);
                        if (slot < NNB) orow0[slot] = (float)(i0base + lane);
                    }
                    c += __popc(mA);
                    if (mB & (1u << lane)) {
                        int slot = c + __popc(mB & below);
                        if (slot < NNB) orow0[slot] = (float)(i0base + 32 + lane);
                    }
                    c += __popc(mB);
                    if (mC & (1u << lane)) {
                        int slot = c + __popc(mC & below);
                        if (slot < NNB) orow0[slot] = (float)(i0base + 64 + lane);
                    }
                    c += __popc(mC);
                    if (mD & (1u << lane)) {
                        int slot = c + __popc(mD & below);
                        if (slot < NNB) orow0[slot] = (float)(i0base + 96 + lane);
                    }
                    c += __popc(mD);
                    cnt0 = c;
                    if (cnt0 >= NNB) {
                        cc02 = KILL;
                        if (lane == 0) atomicAdd(&done_count, 1);
                    }
                }
            }

            // ---- query 1 ----
            {
                uint64_t dA = dist2(xA, yA, zA, ppA, c1x2, c1y2, c1z2, cc12, neg2);
                uint64_t dB = dist2(xB, yB, zB, ppB, c1x2, c1y2, c1z2, cc12, neg2);
                float v0 = lo2(dA), v1 = hi2(dA), v2 = lo2(dB), v3 = hi2(dB);
                bool any = (v0 <= R2) | (v1 <= R2) | (v2 <= R2) | (v3 <= R2);
                if (__any_sync(0xffffffffu, any)) {
                    unsigned mA = __ballot_sync(0xffffffffu, v0 <= R2);
                    unsigned mB = __ballot_sync(0xffffffffu, v1 <= R2);
                    unsigned mC = __ballot_sync(0xffffffffu, v2 <= R2);
                    unsigned mD = __ballot_sync(0xffffffffu, v3 <= R2);
                    const unsigned below = (1u << lane) - 1u;
                    if (cnt1 == 0) {
                        int fi = mA ? i0base + (__ffs(mA) - 1)
                               : mB ? i0base + 32 + (__ffs(mB) - 1)
                               : mC ? i0base + 64 + (__ffs(mC) - 1)
                                    : i0base + 96 + (__ffs(mD) - 1);
                        first1 = (float)fi;
                    }
                    int c = cnt1;
                    if (mA & (1u << lane)) {
                        int slot = c + __popc(mA & below);
                        if (slot < NNB) orow1[slot] = (float)(i0base + lane);
                    }
                    c += __popc(mA);
                    if (mB & (1u << lane)) {
                        int slot = c + __popc(mB & below);
                        if (slot < NNB) orow1[slot] = (float)(i0base + 32 + lane);
                    }
                    c += __popc(mB);
                    if (mC & (1u << lane)) {
                        int slot = c + __popc(mC & below);
                        if (slot < NNB) orow1[slot] = (float)(i0base + 64 + lane);
                    }
                    c += __popc(mC);
                    if (mD & (1u << lane)) {
                        int slot = c + __popc(mD & below);
                        if (slot < NNB) orow1[slot] = (float)(i0base + 96 + lane);
                    }
                    c += __popc(mD);
                    cnt1 = c;
                    if (cnt1 >= NNB) {
                        cc12 = KILL;
                        if (lane == 0) atomicAdd(&done_count, 1);
                    }
                }
            }

            if (cnt0 >= NNB && cnt1 >= NNB) break;
        }
    }

    // Pad tails with first hit (group_first semantics).
    if (cnt0 > NNB) cnt0 = NNB;
    if (cnt1 > NNB) cnt1 = NNB;
    for (int s = cnt0 + lane; s < NNB; s += 32) orow0[s] = first0;
    for (int s = cnt1 + lane; s < NNB; s += 32) orow1[s] = first1;
}

extern "C" void kernel_launch(void* const* d_in, const int* in_sizes, int n_in,
                              void* d_out, int out_size)
{
    const float* pos;
    const int*   cent;
    if (in_sizes[0] > in_sizes[1]) {
        pos  = (const float*)d_in[0];
        cent = (const int*)  d_in[1];
    } else {
        pos  = (const float*)d_in[1];
        cent = (const int*)  d_in[0];
    }
    float* out = (float*)d_out;                  // (8,2048,64) as float32

    dim3 grid(BATCH * NQ / QPB);                 // 1024 blocks
    dim3 block(256);
    frnn_kernel<<<grid, block>>>(pos, cent, out);
}